// round 3
// baseline (speedup 1.0000x reference)
#include <cuda_runtime.h>

// 2-layer GRU (PyTorch semantics) + linear head. T=512, B=4096, I=2, H=64.
// 128 persistent blocks x 512 threads. Each block = 4 INDEPENDENT 128-thread
// sub-blocks, each owning 8 batch rows for the whole sequence (no k-split,
// no cross-sub reduction). Weights shared read-only in SMEM. h states double-
// buffered in SMEM as duplicated float2; all GEMM math in fma.rn.f32x2.
// 2 named barriers (128 threads) per step per sub-block.

#define TT   512
#define BB   4096
#define II   2
#define GG   192      // 3*H
#define BT   32       // batch rows per block
#define NBLK (BB/BT)  // 128
#define NTHR 512
#define BTS  8        // batch rows per sub-block
#define HROW 16       // floats per hd row: 8 batch x (h,h)

typedef unsigned long long u64;

__device__ __forceinline__ void unpack2(u64 v, float& lo, float& hi) {
    asm("mov.b64 {%0,%1}, %2;" : "=f"(lo), "=f"(hi) : "l"(v));
}
__device__ __forceinline__ void ffma2(u64& d, u64 a, u64 b) {
    asm("fma.rn.f32x2 %0, %1, %2, %0;" : "+l"(d) : "l"(a), "l"(b));
}
__device__ __forceinline__ float sigm(float x) {
    return 1.0f / (1.0f + __expf(-x));
}
__device__ __forceinline__ float tanh_(float x) {
    return 1.0f - __fdividef(2.0f, __expf(2.0f * x) + 1.0f);
}

// SMEM layout (float index):
//   w0T [64][192]          Whh0^T        (w0T[k][g] = Whh0[g][k])
//   w1T [128][192]         [Wih1;Whh1]^T (rows 0..63 = Wih1, 64..127 = Whh1)
//   wx  [64][6]            Wih0 rows (r,z,n x 2 inputs)
//   bc0 [64][4], bc1[64][4] combined biases (br, bz, bnx, bnh)
//   hd0 [4 sub][2 buf][64][16]  layer-0 h, duplicated (h,h) per batch
//   hd1 [4 sub][2 buf][64][16]  layer-1 h
#define OFF_W0T 0
#define OFF_W1T (OFF_W0T + 64*GG)        // 12288
#define OFF_WX  (OFF_W1T + 128*GG)       // 36864
#define OFF_BC0 (OFF_WX  + 64*6)         // 37248
#define OFF_BC1 (OFF_BC0 + 64*4)         // 37504
#define OFF_HD0 (OFF_BC1 + 64*4)         // 37760
#define OFF_HD1 (OFF_HD0 + 4*2*64*HROW)  // 45952
#define SMEM_FLOATS (OFF_HD1 + 4*2*64*HROW)  // 54144
#define SMEM_BYTES  (SMEM_FLOATS * 4)        // 216576

#define SUBBAR(id) asm volatile("bar.sync %0, 128;" :: "r"(id) : "memory")

extern "C" __global__ void __launch_bounds__(NTHR, 1)
gru2_kernel(const float* __restrict__ gx,
            const float* __restrict__ Wih0, const float* __restrict__ Whh0,
            const float* __restrict__ bih0, const float* __restrict__ bhh0,
            const float* __restrict__ Wih1, const float* __restrict__ Whh1,
            const float* __restrict__ bih1, const float* __restrict__ bhh1,
            const float* __restrict__ Wp,   const float* __restrict__ bp,
            float* __restrict__ out)
{
    extern __shared__ float sm[];
    float* w0T = sm + OFF_W0T;
    float* w1T = sm + OFF_W1T;
    float* wx  = sm + OFF_WX;
    float* bc0 = sm + OFF_BC0;
    float* bc1 = sm + OFF_BC1;

    const int tid = threadIdx.x;

    // ---- one-time staging ----
    for (int i = tid; i < GG * 64; i += NTHR) {
        int g = i / 64, k = i % 64;
        w0T[k * GG + g]        = Whh0[i];
        w1T[k * GG + g]        = Wih1[i];
        w1T[(64 + k) * GG + g] = Whh1[i];
    }
    for (int j = tid; j < 64; j += NTHR) {
        wx[j*6+0] = Wih0[j*2+0];         wx[j*6+1] = Wih0[j*2+1];
        wx[j*6+2] = Wih0[(64+j)*2+0];    wx[j*6+3] = Wih0[(64+j)*2+1];
        wx[j*6+4] = Wih0[(128+j)*2+0];   wx[j*6+5] = Wih0[(128+j)*2+1];
        bc0[j*4+0] = bih0[j]     + bhh0[j];
        bc0[j*4+1] = bih0[64+j]  + bhh0[64+j];
        bc0[j*4+2] = bih0[128+j];
        bc0[j*4+3] = bhh0[128+j];
        bc1[j*4+0] = bih1[j]     + bhh1[j];
        bc1[j*4+1] = bih1[64+j]  + bhh1[64+j];
        bc1[j*4+2] = bih1[128+j];
        bc1[j*4+3] = bhh1[128+j];
    }
    for (int i = tid; i < SMEM_FLOATS - OFF_HD0; i += NTHR) sm[OFF_HD0 + i] = 0.0f;
    __syncthreads();

    // ---- per-thread mapping ----
    const int sub = tid >> 7;        // 0..3, warps don't straddle subs
    const int ht  = tid & 127;
    const int jpg = ht >> 3;         // 0..15 -> j0 = jpg*4
    const int b   = ht & 7;          // one batch row per thread
    const int j0  = jpg * 4;
    const int bglob = blockIdx.x * BT + sub * BTS + b;
    const int bar_id = sub + 1;

    float* hd0_0 = sm + OFF_HD0 + sub * (2 * 64 * HROW);
    float* hd0_1 = hd0_0 + 64 * HROW;
    float* hd1_0 = sm + OFF_HD1 + sub * (2 * 64 * HROW);
    float* hd1_1 = hd1_0 + 64 * HROW;

    const int boff = b * 2;

    float x0, x1;
    {
        float2 v = *(const float2*)(gx + (size_t)bglob * 2);
        x0 = v.x; x1 = v.y;
    }

    for (int t = 0; t < TT; ++t) {
        float* hd0c = (t & 1) ? hd0_1 : hd0_0;
        float* hd0n = (t & 1) ? hd0_0 : hd0_1;
        float* hd1c = (t & 1) ? hd1_1 : hd1_0;
        float* hd1n = (t & 1) ? hd1_0 : hd1_1;

        // prefetch next x
        float nx0, nx1;
        {
            int tn = (t + 1 < TT) ? t + 1 : t;
            float2 v = *(const float2*)(gx + ((size_t)tn * BB + bglob) * 2);
            nx0 = v.x; nx1 = v.y;
        }

        // ---- layer 0 GEMM: hg = h0(t-1) @ Whh0^T  (j-tile 4, 1 batch row) ----
        u64 aR[2], aZ[2], aN[2];
        aR[0]=aR[1]=aZ[0]=aZ[1]=aN[0]=aN[1]=0ull;
        #pragma unroll 8
        for (int k = 0; k < 64; ++k) {
            const float* wr = w0T + k * GG + j0;
            ulonglong2 wR = *(const ulonglong2*)(wr);
            ulonglong2 wZ = *(const ulonglong2*)(wr + 64);
            ulonglong2 wN = *(const ulonglong2*)(wr + 128);
            u64 h = *(const u64*)(hd0c + k * HROW + boff);
            ffma2(aR[0], h, wR.x); ffma2(aR[1], h, wR.y);
            ffma2(aZ[0], h, wZ.x); ffma2(aZ[1], h, wZ.y);
            ffma2(aN[0], h, wN.x); ffma2(aN[1], h, wN.y);
        }

        // ---- layer 0 gates; write h0(t) to hd0n ----
        #pragma unroll
        for (int jj = 0; jj < 4; ++jj) {
            const int j = j0 + jj;
            float l, h, aRv, aZv, aNv;
            unpack2(aR[jj>>1], l, h); aRv = (jj&1) ? h : l;
            unpack2(aZ[jj>>1], l, h); aZv = (jj&1) ? h : l;
            unpack2(aN[jj>>1], l, h); aNv = (jj&1) ? h : l;
            float r = sigm(aRv + x0*wx[j*6+0] + x1*wx[j*6+1] + bc0[j*4+0]);
            float z = sigm(aZv + x0*wx[j*6+2] + x1*wx[j*6+3] + bc0[j*4+1]);
            float n = tanh_(x0*wx[j*6+4] + x1*wx[j*6+5] + bc0[j*4+2]
                            + r * (aNv + bc0[j*4+3]));
            float hold = hd0c[j * HROW + boff];
            float v = n + z * (hold - n);
            *(float2*)(hd0n + j * HROW + boff) = make_float2(v, v);
        }
        SUBBAR(bar_id);   // h0(t) visible to this sub-block

        // ---- layer 1 fused GEMM: [h0(t); h1(t-1)] @ [Wih1;Whh1]^T ----
        u64 cR[2], cZ[2], cNx[2], cNh[2];
        cR[0]=cR[1]=cZ[0]=cZ[1]=cNx[0]=cNx[1]=cNh[0]=cNh[1]=0ull;
        #pragma unroll 4
        for (int k = 0; k < 64; ++k) {
            const float* wa = w1T + k * GG + j0;          // input side
            const float* wb = w1T + (64 + k) * GG + j0;   // recurrent side
            ulonglong2 waR = *(const ulonglong2*)(wa);
            ulonglong2 waZ = *(const ulonglong2*)(wa + 64);
            ulonglong2 waN = *(const ulonglong2*)(wa + 128);
            ulonglong2 wbR = *(const ulonglong2*)(wb);
            ulonglong2 wbZ = *(const ulonglong2*)(wb + 64);
            ulonglong2 wbN = *(const ulonglong2*)(wb + 128);
            u64 hA = *(const u64*)(hd0n + k * HROW + boff);
            u64 hB = *(const u64*)(hd1c + k * HROW + boff);
            ffma2(cR[0],  hA, waR.x); ffma2(cR[1],  hA, waR.y);
            ffma2(cZ[0],  hA, waZ.x); ffma2(cZ[1],  hA, waZ.y);
            ffma2(cNx[0], hA, waN.x); ffma2(cNx[1], hA, waN.y);
            ffma2(cR[0],  hB, wbR.x); ffma2(cR[1],  hB, wbR.y);
            ffma2(cZ[0],  hB, wbZ.x); ffma2(cZ[1],  hB, wbZ.y);
            ffma2(cNh[0], hB, wbN.x); ffma2(cNh[1], hB, wbN.y);
        }

        // ---- layer 1 gates; write h1(t) to hd1n ----
        #pragma unroll
        for (int jj = 0; jj < 4; ++jj) {
            const int j = j0 + jj;
            float l, h, cRv, cZv, cNxv, cNhv;
            unpack2(cR[jj>>1],  l, h); cRv  = (jj&1) ? h : l;
            unpack2(cZ[jj>>1],  l, h); cZv  = (jj&1) ? h : l;
            unpack2(cNx[jj>>1], l, h); cNxv = (jj&1) ? h : l;
            unpack2(cNh[jj>>1], l, h); cNhv = (jj&1) ? h : l;
            float r = sigm(cRv + bc1[j*4+0]);
            float z = sigm(cZv + bc1[j*4+1]);
            float n = tanh_(cNxv + bc1[j*4+2] + r * (cNhv + bc1[j*4+3]));
            float hold = hd1c[j * HROW + boff];
            float v = n + z * (hold - n);
            *(float2*)(hd1n + j * HROW + boff) = make_float2(v, v);
        }
        SUBBAR(bar_id);   // h1(t) visible; hd*c safe to overwrite next step

        x0 = nx0; x1 = nx1;
    }

    // ---- projection: out[b] = [h0f, h1f] @ Wp^T + bp ----
    // final states are in buffer 0 (written at t=511, buf (512)&1 = 0)
    {
        const int pb  = ht >> 4;     // 0..7 batch row
        const int seg = ht & 15;     // 16 segs x 8 features
        float s = 0.0f;
        #pragma unroll
        for (int i = 0; i < 8; ++i) {
            int c = seg * 8 + i;
            float f = (c < 64) ? hd0_0[c * HROW + pb * 2]
                               : hd1_0[(c - 64) * HROW + pb * 2];
            s += Wp[c] * f;
        }
        s += __shfl_xor_sync(0xffffffffu, s, 1);
        s += __shfl_xor_sync(0xffffffffu, s, 2);
        s += __shfl_xor_sync(0xffffffffu, s, 4);
        s += __shfl_xor_sync(0xffffffffu, s, 8);
        if (seg == 0)
            out[blockIdx.x * BT + sub * BTS + pb] = s + bp[0];
    }
}

extern "C" void kernel_launch(void* const* d_in, const int* in_sizes, int n_in,
                              void* d_out, int out_size)
{
    (void)in_sizes; (void)n_in; (void)out_size;
    const float* x    = (const float*)d_in[0];
    const float* Wih0 = (const float*)d_in[1];
    const float* Whh0 = (const float*)d_in[2];
    const float* bih0 = (const float*)d_in[3];
    const float* bhh0 = (const float*)d_in[4];
    const float* Wih1 = (const float*)d_in[5];
    const float* Whh1 = (const float*)d_in[6];
    const float* bih1 = (const float*)d_in[7];
    const float* bhh1 = (const float*)d_in[8];
    const float* Wp   = (const float*)d_in[9];
    const float* bp   = (const float*)d_in[10];
    float* out = (float*)d_out;

    cudaFuncSetAttribute(gru2_kernel, cudaFuncAttributeMaxDynamicSharedMemorySize, SMEM_BYTES);
    gru2_kernel<<<NBLK, NTHR, SMEM_BYTES>>>(x, Wih0, Whh0, bih0, bhh0,
                                            Wih1, Whh1, bih1, bhh1, Wp, bp, out);
}

// round 4
// speedup vs baseline: 1.4530x; 1.4530x over previous
#include <cuda_runtime.h>

// 2-layer GRU (PyTorch semantics) + linear head. T=512, B=4096, I=2, H=64.
// 128 persistent blocks x 256 threads, BT=32 batch rows per block.
// Tile per thread: 2 j x 8 b, k-split 2 ways inside each warp (lane bit 4).
// f32x2 lanes pack (even-k, odd-k) partial sums -> h loads un-duplicated.
// k-split partials reduced via shfl.bfly(16) in registers (no smem traffic).
// tanh.approx for all gate nonlinearities. 2 barriers per step.

#define TT   512
#define BB   4096
#define NBLK 128
#define NTHR 256

typedef unsigned long long u64;

__device__ __forceinline__ void ffma2(u64& d, u64 a, u64 b) {
    asm("fma.rn.f32x2 %0, %1, %2, %0;" : "+l"(d) : "l"(a), "l"(b));
}
__device__ __forceinline__ void fadd2(u64& d, u64 a) {
    asm("add.rn.f32x2 %0, %0, %1;" : "+l"(d) : "l"(a));
}
__device__ __forceinline__ float fold(u64 v) {
    float lo, hi;
    asm("mov.b64 {%0,%1}, %2;" : "=f"(lo), "=f"(hi) : "l"(v));
    return lo + hi;
}
__device__ __forceinline__ float tanh_(float x) {
    float r; asm("tanh.approx.f32 %0, %1;" : "=f"(r) : "f"(x)); return r;
}
__device__ __forceinline__ float sigm(float x) {
    return fmaf(tanh_(0.5f * x), 0.5f, 0.5f);
}

// k-split exchange: sum my-jj accums with partner's (R,Z and layer0 N)
__device__ __forceinline__ float exadd(u64 a0, u64 a1, int ks) {
    u64 snd  = ks ? a0 : a1;     // what partner needs (its jj)
    u64 mine = ks ? a1 : a0;     // my jj
    u64 rcv  = __shfl_xor_sync(0xffffffffu, snd, 16);
    fadd2(mine, rcv);
    return fold(mine);
}
// layer-1 N gate: ks0 holds input-side partial, ks1 recurrent-side; no add.
__device__ __forceinline__ void exn(u64 a0, u64 a1, int ks, float& nx, float& nh) {
    u64 snd  = ks ? a0 : a1;
    u64 mine = ks ? a1 : a0;
    u64 rcv  = __shfl_xor_sync(0xffffffffu, snd, 16);
    float fm = fold(mine), fr = fold(rcv);
    nx = ks ? fr : fm;
    nh = ks ? fm : fr;
}

// SMEM layout (floats):
//   w0p [32 kp][192 g][2 e] : w0p[kp][g][e] = Whh0[g][2kp+e]          (12288)
//   w1p [64 kp][192 g][2 e] : kp<32 -> Wih1[g][2kp+e], else Whh1      (24576)
//   hp0 [2 buf][32 kp][32 b][2 e]  layer-0 h, k-pair packed           ( 4096)
//   hp1A[2 buf][32][32][2]  layer-1 input-side h (= fresh h0)         ( 4096)
//   hp1B[2 buf][32][32][2]  layer-1 recurrent h (= h1)                ( 4096)
#define OFF_W0P  0
#define OFF_W1P  12288
#define OFF_HP0  36864
#define OFF_HP1A 40960
#define OFF_HP1B 45056
#define SMEM_FLOATS 49152
#define SMEM_BYTES  (SMEM_FLOATS * 4)   // 196608

template<int NKP>
__device__ __forceinline__ void gemmkp(const float* __restrict__ wb,
                                       const float* __restrict__ hb,
                                       int j0, int b0,
                                       u64 aR[2][8], u64 aZ[2][8], u64 aN[2][8])
{
    #pragma unroll 4
    for (int kp = 0; kp < NKP; ++kp) {
        const float* wr = wb + kp * 384 + j0 * 2;
        ulonglong2 wR = *(const ulonglong2*)(wr);          // (j0 pair, j0+1 pair)
        ulonglong2 wZ = *(const ulonglong2*)(wr + 128);
        ulonglong2 wN = *(const ulonglong2*)(wr + 256);
        const float* hr = hb + (kp * 32 + b0) * 2;
        ulonglong2 h01 = *(const ulonglong2*)(hr);
        ulonglong2 h23 = *(const ulonglong2*)(hr + 4);
        ulonglong2 h45 = *(const ulonglong2*)(hr + 8);
        ulonglong2 h67 = *(const ulonglong2*)(hr + 12);
        u64 hv[8] = { h01.x, h01.y, h23.x, h23.y, h45.x, h45.y, h67.x, h67.y };
        #pragma unroll
        for (int b = 0; b < 8; ++b) {
            ffma2(aR[0][b], hv[b], wR.x); ffma2(aR[1][b], hv[b], wR.y);
            ffma2(aZ[0][b], hv[b], wZ.x); ffma2(aZ[1][b], hv[b], wZ.y);
            ffma2(aN[0][b], hv[b], wN.x); ffma2(aN[1][b], hv[b], wN.y);
        }
    }
}

extern "C" __global__ void __launch_bounds__(NTHR, 1)
gru2_kernel(const float* __restrict__ gx,
            const float* __restrict__ Wih0, const float* __restrict__ Whh0,
            const float* __restrict__ bih0, const float* __restrict__ bhh0,
            const float* __restrict__ Wih1, const float* __restrict__ Whh1,
            const float* __restrict__ bih1, const float* __restrict__ bhh1,
            const float* __restrict__ Wp,   const float* __restrict__ bp,
            float* __restrict__ out)
{
    extern __shared__ __align__(16) float sm[];
    float* w0p  = sm + OFF_W0P;
    float* w1p  = sm + OFF_W1P;
    float* hp0  = sm + OFF_HP0;
    float* hp1A = sm + OFF_HP1A;
    float* hp1B = sm + OFF_HP1B;

    const int tid = threadIdx.x;

    // ---- one-time weight staging (k-pair interleaved) ----
    for (int i = tid; i < 12288; i += NTHR) {
        int e = i & 1, g = (i >> 1) % 192, kp = i / 384;
        w0p[i] = Whh0[g * 64 + 2 * kp + e];
    }
    for (int i = tid; i < 24576; i += NTHR) {
        int e = i & 1, g = (i >> 1) % 192, kp = i / 384;
        w1p[i] = (kp < 32) ? Wih1[g * 64 + 2 * kp + e]
                           : Whh1[g * 64 + 2 * (kp - 32) + e];
    }
    for (int i = tid; i < 12288; i += NTHR) sm[OFF_HP0 + i] = 0.0f;

    // ---- per-thread mapping ----
    const int w    = tid >> 5;
    const int lane = tid & 31;
    const int ks   = lane >> 4;          // k-split half
    const int jq   = (lane >> 2) & 3;
    const int bg   = lane & 3;
    const int jp   = w * 4 + jq;         // 0..31 j-pair index
    const int j0   = jp * 2;
    const int myj  = j0 + ks;            // j this thread finalizes
    const int b0   = bg * 8;
    const int bglob0 = blockIdx.x * 32 + b0;

    // per-thread constants (registers)
    const float wxr0 = Wih0[myj*2],       wxr1 = Wih0[myj*2+1];
    const float wxz0 = Wih0[(64+myj)*2],  wxz1 = Wih0[(64+myj)*2+1];
    const float wxn0 = Wih0[(128+myj)*2], wxn1 = Wih0[(128+myj)*2+1];
    const float br0 = bih0[myj]    + bhh0[myj];
    const float bz0 = bih0[64+myj] + bhh0[64+myj];
    const float bnx0 = bih0[128+myj], bnh0 = bhh0[128+myj];
    const float br1 = bih1[myj]    + bhh1[myj];
    const float bz1 = bih1[64+myj] + bhh1[64+myj];
    const float bnx1 = bih1[128+myj], bnh1 = bhh1[128+myj];

    float hprev0[8], hprev1[8];
    #pragma unroll
    for (int b = 0; b < 8; ++b) { hprev0[b] = 0.0f; hprev1[b] = 0.0f; }

    __syncthreads();

    for (int t = 0; t < TT; ++t) {
        const int cur = t & 1, nxt = cur ^ 1;

        // x for my 8 batch rows (consumed in L0 elementwise; latency hidden by GEMM)
        float4 xq[4];
        {
            const float4* xp = (const float4*)(gx + ((size_t)t * BB + bglob0) * 2);
            xq[0] = xp[0]; xq[1] = xp[1]; xq[2] = xp[2]; xq[3] = xp[3];
        }

        // ================= layer 0 GEMM (my k-half: 16 k-pairs) =================
        u64 aR[2][8], aZ[2][8], aN[2][8];
        #pragma unroll
        for (int b = 0; b < 8; ++b) {
            aR[0][b]=0; aR[1][b]=0; aZ[0][b]=0; aZ[1][b]=0; aN[0][b]=0; aN[1][b]=0;
        }
        gemmkp<16>(w0p + ks * (16 * 384), hp0 + cur * 2048 + ks * 1024,
                   j0, b0, aR, aZ, aN);

        // ---- layer 0 reduce (shfl) + gates; write h0(t) ----
        {
            float* h0n = hp0  + nxt * 2048;
            float* h1a = hp1A + cur * 2048;
            #pragma unroll
            for (int b = 0; b < 8; ++b) {
                float sR = exadd(aR[0][b], aR[1][b], ks);
                float sZ = exadd(aZ[0][b], aZ[1][b], ks);
                float sN = exadd(aN[0][b], aN[1][b], ks);
                const float4 xv = xq[b >> 1];
                const float x0 = (b & 1) ? xv.z : xv.x;
                const float x1 = (b & 1) ? xv.w : xv.y;
                float r = sigm(sR + x0 * wxr0 + x1 * wxr1 + br0);
                float z = sigm(sZ + x0 * wxz0 + x1 * wxz1 + bz0);
                float n = tanh_(x0 * wxn0 + x1 * wxn1 + bnx0 + r * (sN + bnh0));
                float h = n + z * (hprev0[b] - n);
                hprev0[b] = h;
                const int idx = (jp * 32 + b0 + b) * 2 + ks;
                h0n[idx] = h;
                h1a[idx] = h;
            }
        }
        __syncthreads();   // h0(t) visible for layer-1 input side

        // ====== layer 1 GEMM (ks0: input side over fresh h0; ks1: recurrent h1) ======
        u64 cR[2][8], cZ[2][8], cN[2][8];
        #pragma unroll
        for (int b = 0; b < 8; ++b) {
            cR[0][b]=0; cR[1][b]=0; cZ[0][b]=0; cZ[1][b]=0; cN[0][b]=0; cN[1][b]=0;
        }
        {
            const float* hb1 = ks ? (hp1B + nxt * 2048)   // h1(t-1)
                                  : (hp1A + cur * 2048);  // h0(t)
            gemmkp<32>(w1p + ks * (32 * 384), hb1, j0, b0, cR, cZ, cN);
        }

        // ---- layer 1 reduce + gates; write h1(t) ----
        {
            float* h1b = hp1B + cur * 2048;
            #pragma unroll
            for (int b = 0; b < 8; ++b) {
                float sR = exadd(cR[0][b], cR[1][b], ks);
                float sZ = exadd(cZ[0][b], cZ[1][b], ks);
                float nx, nh; exn(cN[0][b], cN[1][b], ks, nx, nh);
                float r = sigm(sR + br1);
                float z = sigm(sZ + bz1);
                float n = tanh_(nx + bnx1 + r * (nh + bnh1));
                float h = n + z * (hprev1[b] - n);
                hprev1[b] = h;
                h1b[(jp * 32 + b0 + b) * 2 + ks] = h;
            }
        }
        __syncthreads();   // h1(t) visible; buffers safe for reuse
    }

    // ---- projection: out[b] = [h0f, h1f] @ Wp^T + bp ----
    // final states live in hprev0/hprev1 registers; reduce across j via smem scratch
    {
        float* scr = sm + OFF_HP0;   // reuse, [32 b][64 j]
        const float wp0 = Wp[myj], wp1 = Wp[64 + myj];
        #pragma unroll
        for (int b = 0; b < 8; ++b)
            scr[(b0 + b) * 64 + myj] = wp0 * hprev0[b] + wp1 * hprev1[b];
        __syncthreads();
        if (tid < 32) {
            float s = bp[0];
            #pragma unroll 8
            for (int j = 0; j < 64; ++j) s += scr[tid * 64 + j];
            out[blockIdx.x * 32 + tid] = s;
        }
    }
}

extern "C" void kernel_launch(void* const* d_in, const int* in_sizes, int n_in,
                              void* d_out, int out_size)
{
    (void)in_sizes; (void)n_in; (void)out_size;
    const float* x    = (const float*)d_in[0];
    const float* Wih0 = (const float*)d_in[1];
    const float* Whh0 = (const float*)d_in[2];
    const float* bih0 = (const float*)d_in[3];
    const float* bhh0 = (const float*)d_in[4];
    const float* Wih1 = (const float*)d_in[5];
    const float* Whh1 = (const float*)d_in[6];
    const float* bih1 = (const float*)d_in[7];
    const float* bhh1 = (const float*)d_in[8];
    const float* Wp   = (const float*)d_in[9];
    const float* bp   = (const float*)d_in[10];
    float* out = (float*)d_out;

    cudaFuncSetAttribute(gru2_kernel, cudaFuncAttributeMaxDynamicSharedMemorySize, SMEM_BYTES);
    gru2_kernel<<<NBLK, NTHR, SMEM_BYTES>>>(x, Wih0, Whh0, bih0, bhh0,
                                            Wih1, Whh1, bih1, bhh1, Wp, bp, out);
}

// round 5
// speedup vs baseline: 1.4557x; 1.0018x over previous
#include <cuda_runtime.h>

// 2-layer GRU (PyTorch semantics) + linear head. T=512, B=4096, I=2, H=64.
// 128 persistent blocks x 512 threads (4 warps/SMSP). Each thread: 1 j-column,
// 8 batch rows in the GEMM, 4 at gate-finalize (ks-pair split via shfl.bfly 16).
// f32x2 lanes pack (even-k, odd-k) partial sums. SMEM fully bank-swizzled:
// per-bg +8-float region shift, +4/+8-float pads between ks halves -> 1-phase LDS.

#define TT   512
#define BB   4096
#define NBLK 128
#define NTHR 512

typedef unsigned long long u64;

// SMEM offsets (floats)
// w0p: Whh0 k-pair packed, 2 ks halves (16 kp x [192 g][2 e]), ks1 at +6152 (+8 bank pad)
// w1p: [Wih1 | Whh1], halves of 32 kp x 384, ks1 at +12296 (+8 bank pad)
// hp0: layer0 h, 2 bufs x (2 ks-halves of 16 kp x 72-fl rows, ks1 at +1156)
// hp1A: fresh h0 for layer1 input side, 32 kp x 72 (single buffer)
// hp1B: h1, 2 bufs x 2304, base at hp1A+2308 (+4 bank pad)
#define OFF_W0P  0
#define OFF_W1P  12320
#define OFF_HP0  36928
#define OFF_HP1A 41568
#define OFF_HP1B 43876
#define SMEM_FLOATS 48484
#define SMEM_BYTES (SMEM_FLOATS * 4)   // 193936

__device__ __forceinline__ void ffma2(u64& d, u64 a, u64 b) {
    asm("fma.rn.f32x2 %0, %1, %2, %0;" : "+l"(d) : "l"(a), "l"(b));
}
__device__ __forceinline__ void fadd2(u64& d, u64 a) {
    asm("add.rn.f32x2 %0, %0, %1;" : "+l"(d) : "l"(a));
}
__device__ __forceinline__ float fold(u64 v) {
    float lo, hi;
    asm("mov.b64 {%0,%1}, %2;" : "=f"(lo), "=f"(hi) : "l"(v));
    return lo + hi;
}
__device__ __forceinline__ float tanh_(float x) {
    float r; asm("tanh.approx.f32 %0, %1;" : "=f"(r) : "f"(x)); return r;
}
__device__ __forceinline__ float sigm(float x) {
    return fmaf(tanh_(0.5f * x), 0.5f, 0.5f);
}
__device__ __forceinline__ float pairsum(u64 keep, u64 snd) {
    u64 rcv = __shfl_xor_sync(0xffffffffu, snd, 16);
    fadd2(keep, rcv);
    return fold(keep);
}

// GEMM over NKP k-pairs: wb includes (ks half + j*2), hb includes (ks half + region)
template<int NKP>
__device__ __forceinline__ void gemmkp(const float* __restrict__ wb,
                                       const float* __restrict__ hb,
                                       u64 aR[8], u64 aZ[8], u64 aN[8])
{
    #pragma unroll 4
    for (int kp = 0; kp < NKP; ++kp) {
        u64 wR = *(const u64*)(wb + kp * 384);
        u64 wZ = *(const u64*)(wb + kp * 384 + 128);
        u64 wN = *(const u64*)(wb + kp * 384 + 256);
        const float* hr = hb + kp * 72;
        ulonglong2 h01 = *(const ulonglong2*)(hr);
        ulonglong2 h23 = *(const ulonglong2*)(hr + 4);
        ulonglong2 h45 = *(const ulonglong2*)(hr + 8);
        ulonglong2 h67 = *(const ulonglong2*)(hr + 12);
        u64 hv[8] = { h01.x, h01.y, h23.x, h23.y, h45.x, h45.y, h67.x, h67.y };
        #pragma unroll
        for (int b = 0; b < 8; ++b) {
            ffma2(aR[b], hv[b], wR);
            ffma2(aZ[b], hv[b], wZ);
            ffma2(aN[b], hv[b], wN);
        }
    }
}

extern "C" __global__ void __launch_bounds__(NTHR, 1)
gru2_kernel(const float* __restrict__ gx,
            const float* __restrict__ Wih0, const float* __restrict__ Whh0,
            const float* __restrict__ bih0, const float* __restrict__ bhh0,
            const float* __restrict__ Wih1, const float* __restrict__ Whh1,
            const float* __restrict__ bih1, const float* __restrict__ bhh1,
            const float* __restrict__ Wp,   const float* __restrict__ bp,
            float* __restrict__ out)
{
    extern __shared__ __align__(16) float sm[];
    const int tid = threadIdx.x;

    // ---- one-time weight staging (k-pair interleaved, ks halves padded) ----
    for (int i = tid; i < 12288; i += NTHR) {
        int e = i & 1, g = (i >> 1) % 192, kp = i / 384;
        int ks_ = kp >> 4, kpl = kp & 15;
        sm[OFF_W0P + ks_ * 6152 + kpl * 384 + g * 2 + e] = Whh0[g * 64 + kp * 2 + e];
    }
    for (int i = tid; i < 24576; i += NTHR) {
        int e = i & 1, g = (i >> 1) % 192, kp = i / 384;
        int half = kp >> 5, kpl = kp & 31;
        sm[OFF_W1P + half * 12296 + kpl * 384 + g * 2 + e] =
            (half ? Whh1 : Wih1)[g * 64 + kpl * 2 + e];
    }
    for (int i = tid; i < SMEM_FLOATS - OFF_HP0; i += NTHR) sm[OFF_HP0 + i] = 0.0f;

    // ---- per-thread mapping ----
    const int warp = tid >> 5;
    const int lane = tid & 31;
    const int ks   = (lane >> 4) & 1;   // k-split / b-split half
    const int jq   = (lane >> 2) & 3;
    const int bg   = lane & 3;
    const int j    = warp * 4 + jq;     // my j column (0..63)
    const int kpj  = j >> 1, ej = j & 1;
    const int RB   = bg * 16 + 8 * (bg >> 1);   // swizzled region base
    const int bf0  = bg * 8 + ks * 4;           // first of my 4 finalized b
    const int bglob = blockIdx.x * 32 + bf0;

    // per-thread gate constants
    const float wxr0 = Wih0[j*2],       wxr1 = Wih0[j*2+1];
    const float wxz0 = Wih0[(64+j)*2],  wxz1 = Wih0[(64+j)*2+1];
    const float wxn0 = Wih0[(128+j)*2], wxn1 = Wih0[(128+j)*2+1];
    const float br0 = bih0[j]    + bhh0[j];
    const float bz0 = bih0[64+j] + bhh0[64+j];
    const float bnx0 = bih0[128+j], bnh0 = bhh0[128+j];
    const float br1 = bih1[j]    + bhh1[j];
    const float bz1 = bih1[64+j] + bhh1[64+j];
    const float bnx1 = bih1[128+j], bnh1 = bhh1[128+j];

    // weight base pointers (include ks half + my j)
    const float* wb0 = sm + OFF_W0P + ks * 6152  + j * 2;
    const float* wb1 = sm + OFF_W1P + ks * 12296 + j * 2;

    // h store offsets (exclude buffer toggle)
    const int st0_off = OFF_HP0 + ((j < 32) ? kpj * 72 : 1156 + (kpj - 16) * 72)
                        + RB + ks * 8 + ej;
    float* st1a = sm + OFF_HP1A + kpj * 72 + RB + ks * 8 + ej;
    const int st1b_off = OFF_HP1B + kpj * 72 + RB + ks * 8 + ej;

    float hprev0[4] = {0.f, 0.f, 0.f, 0.f};
    float hprev1[4] = {0.f, 0.f, 0.f, 0.f};

    __syncthreads();

    for (int t = 0; t < TT; ++t) {
        const int cur = t & 1, nxt = cur ^ 1;

        // x(t) for my 4 batch rows
        const float* xb = gx + ((size_t)t * BB + bglob) * 2;
        float4 xq0 = *(const float4*)(xb);
        float4 xq1 = *(const float4*)(xb + 4);
        float xf[8] = { xq0.x, xq0.y, xq0.z, xq0.w, xq1.x, xq1.y, xq1.z, xq1.w };

        // ================= layer 0 GEMM (my ks half: 16 k-pairs) =================
        u64 aR[8], aZ[8], aN[8];
        #pragma unroll
        for (int b = 0; b < 8; ++b) { aR[b] = 0; aZ[b] = 0; aN[b] = 0; }
        gemmkp<16>(wb0, sm + OFF_HP0 + cur * 2320 + ks * 1156 + RB, aR, aZ, aN);

        // ---- layer 0 pair-exchange + gates; write h0(t) ----
        {
            float* st0 = sm + nxt * 2320 + st0_off;
            #pragma unroll
            for (int i = 0; i < 4; ++i) {
                u64 keepR = ks ? aR[4+i] : aR[i], sndR = ks ? aR[i] : aR[4+i];
                u64 keepZ = ks ? aZ[4+i] : aZ[i], sndZ = ks ? aZ[i] : aZ[4+i];
                u64 keepN = ks ? aN[4+i] : aN[i], sndN = ks ? aN[i] : aN[4+i];
                float sR = pairsum(keepR, sndR);
                float sZ = pairsum(keepZ, sndZ);
                float sN = pairsum(keepN, sndN);
                float x0 = xf[2*i], x1 = xf[2*i+1];
                float r = sigm(sR + x0 * wxr0 + x1 * wxr1 + br0);
                float z = sigm(sZ + x0 * wxz0 + x1 * wxz1 + bz0);
                float n = tanh_(x0 * wxn0 + x1 * wxn1 + bnx0 + r * (sN + bnh0));
                float h = n + z * (hprev0[i] - n);
                hprev0[i] = h;
                st0[i * 2]  = h;
                st1a[i * 2] = h;
            }
        }
        __syncthreads();   // h0(t) visible for layer-1 input side

        // ===== layer 1 GEMM (ks0: input side over fresh h0; ks1: recurrent h1) =====
        u64 cR[8], cZ[8], cN[8];
        #pragma unroll
        for (int b = 0; b < 8; ++b) { cR[b] = 0; cZ[b] = 0; cN[b] = 0; }
        {
            const float* hb1 = ks ? (sm + OFF_HP1B + nxt * 2304 + RB)
                                  : (sm + OFF_HP1A + RB);
            gemmkp<32>(wb1, hb1, cR, cZ, cN);
        }

        // ---- layer 1 pair-exchange + gates; write h1(t) ----
        {
            float* st1 = sm + cur * 2304 + st1b_off;
            #pragma unroll
            for (int i = 0; i < 4; ++i) {
                u64 keepR = ks ? cR[4+i] : cR[i], sndR = ks ? cR[i] : cR[4+i];
                u64 keepZ = ks ? cZ[4+i] : cZ[i], sndZ = ks ? cZ[i] : cZ[4+i];
                u64 keepN = ks ? cN[4+i] : cN[i], sndN = ks ? cN[i] : cN[4+i];
                float sR = pairsum(keepR, sndR);
                float sZ = pairsum(keepZ, sndZ);
                u64 rcvN = __shfl_xor_sync(0xffffffffu, sndN, 16);
                float fm = fold(keepN), fr = fold(rcvN);
                float nx = ks ? fr : fm;
                float nh = ks ? fm : fr;
                float r = sigm(sR + br1);
                float z = sigm(sZ + bz1);
                float n = tanh_(nx + bnx1 + r * (nh + bnh1));
                float h = n + z * (hprev1[i] - n);
                hprev1[i] = h;
                st1[i * 2] = h;
            }
        }
        __syncthreads();   // h1(t) visible; buffers safe for reuse
    }

    // ---- projection: out[b] = sum_j Wp[j]*h0f + Wp[64+j]*h1f + bp ----
    {
        float* scr = sm;   // reuse weight region, [32 b][stride 68]
        const float wp0 = Wp[j], wp1 = Wp[64 + j];
        #pragma unroll
        for (int i = 0; i < 4; ++i)
            scr[(bf0 + i) * 68 + j] = wp0 * hprev0[i] + wp1 * hprev1[i];
        __syncthreads();
        if (tid < 32) {
            float s = bp[0];
            #pragma unroll 8
            for (int jj = 0; jj < 64; ++jj) s += scr[tid * 68 + jj];
            out[blockIdx.x * 32 + tid] = s;
        }
    }
}

extern "C" void kernel_launch(void* const* d_in, const int* in_sizes, int n_in,
                              void* d_out, int out_size)
{
    (void)in_sizes; (void)n_in; (void)out_size;
    const float* x    = (const float*)d_in[0];
    const float* Wih0 = (const float*)d_in[1];
    const float* Whh0 = (const float*)d_in[2];
    const float* bih0 = (const float*)d_in[3];
    const float* bhh0 = (const float*)d_in[4];
    const float* Wih1 = (const float*)d_in[5];
    const float* Whh1 = (const float*)d_in[6];
    const float* bih1 = (const float*)d_in[7];
    const float* bhh1 = (const float*)d_in[8];
    const float* Wp   = (const float*)d_in[9];
    const float* bp   = (const float*)d_in[10];
    float* out = (float*)d_out;

    cudaFuncSetAttribute(gru2_kernel, cudaFuncAttributeMaxDynamicSharedMemorySize, SMEM_BYTES);
    gru2_kernel<<<NBLK, NTHR, SMEM_BYTES>>>(x, Wih0, Whh0, bih0, bhh0,
                                            Wih1, Whh1, bih1, bhh1, Wp, bp, out);
}

// round 6
// speedup vs baseline: 1.7546x; 1.2053x over previous
#include <cuda_runtime.h>

// 2-layer GRU (PyTorch semantics) + linear head. T=512, B=4096, I=2, H=64.
// 128 persistent blocks x 512 threads. Block = TWO independent 256-thread
// groups, each owning 16 batch rows end-to-end; groups share only the
// read-only weights in SMEM and are synchronized ONLY by a group-local named
// barrier (1 per timestep) -> groups drift and cover each other's latency
// phases (GEMM load stalls vs gate MUFU/shfl chains).
// Per-thread tile: 1 j-column x 8 batch rows, k-split 2 ways in-warp (lane
// bit 4), f32x2 lanes pack (even-k, odd-k); reduction via shfl.bfly(16).

#define TT   512
#define BB   4096
#define NBLK 128
#define NTHR 512

typedef unsigned long long u64;

// SMEM (floats):
//  w0 [32 kp][384]: per kp: RZ block (64 j x {R u64, Z u64} = 256 fl) + N (64 j x u64 = 128 fl)
//  w1 [64 kp][384]: kp<32 = Wih1, kp>=32 = Whh1, same per-kp format
//  h  [2 group][hp0 2x1024 | hp1 2x1024]   rows: [kp 0..31][b_local 0..15][e]
#define OFF_W0 0
#define OFF_W1 12288
#define OFF_H  36864
#define SMEM_FLOATS (OFF_H + 2*4096)
#define SMEM_BYTES  (SMEM_FLOATS * 4)   // 180224

__device__ __forceinline__ void ffma2(u64& d, u64 a, u64 b) {
    asm("fma.rn.f32x2 %0, %1, %2, %0;" : "+l"(d) : "l"(a), "l"(b));
}
__device__ __forceinline__ void fadd2(u64& d, u64 a) {
    asm("add.rn.f32x2 %0, %0, %1;" : "+l"(d) : "l"(a));
}
__device__ __forceinline__ float fold(u64 v) {
    float lo, hi;
    asm("mov.b64 {%0,%1}, %2;" : "=f"(lo), "=f"(hi) : "l"(v));
    return lo + hi;
}
__device__ __forceinline__ float tanh_(float x) {
    float r; asm("tanh.approx.f32 %0, %1;" : "=f"(r) : "f"(x)); return r;
}
__device__ __forceinline__ float sigm(float x) {
    return fmaf(tanh_(0.5f * x), 0.5f, 0.5f);
}

#define GRPBAR(id) asm volatile("bar.sync %0, 256;" :: "r"(id) : "memory")

// GEMM over NKP k-pairs. wrz points at (base + kp0*384 + j*4), wn at
// (base + kp0*384 + 256 + j*2), hb at (h rows base + bg*16). Stride 384/32.
template<int NKP>
__device__ __forceinline__ void gemm_rzn(const float* __restrict__ wrz,
                                         const float* __restrict__ wn,
                                         const float* __restrict__ hb,
                                         u64 aR[8], u64 aZ[8], u64 aN[8])
{
    #pragma unroll 4
    for (int kp = 0; kp < NKP; ++kp) {
        ulonglong2 wv = *(const ulonglong2*)(wrz + kp * 384);
        u64 wNv = *(const u64*)(wn + kp * 384);
        const float* hr = hb + kp * 32;
        ulonglong2 h01 = *(const ulonglong2*)(hr);
        ulonglong2 h23 = *(const ulonglong2*)(hr + 4);
        ulonglong2 h45 = *(const ulonglong2*)(hr + 8);
        ulonglong2 h67 = *(const ulonglong2*)(hr + 12);
        u64 hv[8] = { h01.x, h01.y, h23.x, h23.y, h45.x, h45.y, h67.x, h67.y };
        #pragma unroll
        for (int b = 0; b < 8; ++b) {
            ffma2(aR[b], hv[b], wv.x);
            ffma2(aZ[b], hv[b], wv.y);
            ffma2(aN[b], hv[b], wNv);
        }
    }
}

extern "C" __global__ void __launch_bounds__(NTHR, 1)
gru2_kernel(const float* __restrict__ gx,
            const float* __restrict__ Wih0, const float* __restrict__ Whh0,
            const float* __restrict__ bih0, const float* __restrict__ bhh0,
            const float* __restrict__ Wih1, const float* __restrict__ Whh1,
            const float* __restrict__ bih1, const float* __restrict__ bhh1,
            const float* __restrict__ Wp,   const float* __restrict__ bp,
            float* __restrict__ out)
{
    extern __shared__ __align__(16) float sm[];
    const int tid = threadIdx.x;

    // ---- one-time weight staging ----
    // w0: per kp: [j 0..63]{R e0,e1, Z e0,e1} then [j 0..63]{N e0,e1}
    for (int i = tid; i < 12288; i += NTHR) {
        int kp = i / 384, r = i % 384;
        float v;
        if (r < 256) {
            int j = r >> 2, sub = r & 3, gate = sub >> 1, e = sub & 1;
            v = Whh0[(gate * 64 + j) * 64 + 2 * kp + e];
        } else {
            int rr = r - 256, j = rr >> 1, e = rr & 1;
            v = Whh0[(128 + j) * 64 + 2 * kp + e];
        }
        sm[OFF_W0 + i] = v;
    }
    for (int i = tid; i < 24576; i += NTHR) {
        int kp = i / 384, r = i % 384;
        const float* W = (kp < 32) ? Wih1 : Whh1;
        int k0 = 2 * (kp & 31);
        float v;
        if (r < 256) {
            int j = r >> 2, sub = r & 3, gate = sub >> 1, e = sub & 1;
            v = W[(gate * 64 + j) * 64 + k0 + e];
        } else {
            int rr = r - 256, j = rr >> 1, e = rr & 1;
            v = W[(128 + j) * 64 + k0 + e];
        }
        sm[OFF_W1 + i] = v;
    }
    for (int i = tid; i < 2 * 4096; i += NTHR) sm[OFF_H + i] = 0.0f;

    // ---- per-thread mapping ----
    const int g      = tid >> 8;            // group 0/1 (warps 0-7 | 8-15)
    const int gtid   = tid & 255;
    const int warp_g = gtid >> 5;           // 0..7
    const int lane   = tid & 31;
    const int ks     = (lane >> 4) & 1;     // k-split half
    const int jq     = (lane >> 1) & 7;
    const int bg     = lane & 1;            // 2 regions x 8 batch rows
    const int j      = warp_g * 8 + jq;     // my j column (0..63)
    const int kpj    = j >> 1, ej = j & 1;
    const int blf0   = bg * 8 + ks * 4;     // first finalized local b (of 16)
    const int bglob  = blockIdx.x * 32 + g * 16 + blf0;
    const int bar_id = g + 1;

    // gate constants
    const float wxr0 = Wih0[j*2],       wxr1 = Wih0[j*2+1];
    const float wxz0 = Wih0[(64+j)*2],  wxz1 = Wih0[(64+j)*2+1];
    const float wxn0 = Wih0[(128+j)*2], wxn1 = Wih0[(128+j)*2+1];
    const float br0 = bih0[j]    + bhh0[j];
    const float bz0 = bih0[64+j] + bhh0[64+j];
    const float bnx0 = bih0[128+j], bnh0 = bhh0[128+j];
    const float br1 = bih1[j]    + bhh1[j];
    const float bz1 = bih1[64+j] + bhh1[64+j];
    const float bnx1 = bih1[128+j], bnh1 = bhh1[128+j];

    // weight pointers (constant over t)
    const float* w0rz = sm + OFF_W0 + (ks * 16) * 384 + j * 4;
    const float* w0n  = sm + OFF_W0 + (ks * 16) * 384 + 256 + j * 2;
    const float* w1rz = sm + OFF_W1 + (ks * 32) * 384 + j * 4;
    const float* w1n  = sm + OFF_W1 + (ks * 32) * 384 + 256 + j * 2;

    // group h arrays
    float* hp0 = sm + OFF_H + g * 4096;         // 2 bufs x 1024
    float* hp1 = hp0 + 2048;                    // 2 bufs x 1024
    const int bgf = bg * 16;                    // float offset of my b-region in a row

    float hprev0[4] = {0.f, 0.f, 0.f, 0.f};
    float hprev1[4] = {0.f, 0.f, 0.f, 0.f};

    __syncthreads();

    for (int t = 0; t < TT; ++t) {
        const int cur = t & 1, nxt = cur ^ 1;
        float* hp0c = hp0 + cur * 1024;
        float* hp0n = hp0 + nxt * 1024;
        float* hp1c = hp1 + cur * 1024;
        float* hp1n = hp1 + nxt * 1024;

        // x(t) for my 4 finalized batch rows
        const float* xb = gx + ((size_t)t * BB + bglob) * 2;
        float4 xq0 = *(const float4*)(xb);
        float4 xq1 = *(const float4*)(xb + 4);
        float xf[8] = { xq0.x, xq0.y, xq0.z, xq0.w, xq1.x, xq1.y, xq1.z, xq1.w };

        // ======== G0: layer-0 GEMM, my k-half (16 kp) over hp0[cur] ========
        u64 aR[8], aZ[8], aN[8];
        #pragma unroll
        for (int b = 0; b < 8; ++b) { aR[b] = 0; aZ[b] = 0; aN[b] = 0; }
        gemm_rzn<16>(w0rz, w0n, hp0c + (ks * 16) * 32 + bgf, aR, aZ, aN);

        // ======== E0: exchange + gates; write h0(t) -> hp0[nxt] ========
        #pragma unroll
        for (int i = 0; i < 4; ++i) {
            u64 keepR = ks ? aR[4+i] : aR[i], sndR = ks ? aR[i] : aR[4+i];
            u64 keepZ = ks ? aZ[4+i] : aZ[i], sndZ = ks ? aZ[i] : aZ[4+i];
            u64 keepN = ks ? aN[4+i] : aN[i], sndN = ks ? aN[i] : aN[4+i];
            fadd2(keepR, __shfl_xor_sync(0xffffffffu, sndR, 16));
            fadd2(keepZ, __shfl_xor_sync(0xffffffffu, sndZ, 16));
            fadd2(keepN, __shfl_xor_sync(0xffffffffu, sndN, 16));
            float sR = fold(keepR), sZ = fold(keepZ), sN = fold(keepN);
            float x0 = xf[2*i], x1 = xf[2*i+1];
            float r = sigm(sR + x0 * wxr0 + x1 * wxr1 + br0);
            float z = sigm(sZ + x0 * wxz0 + x1 * wxz1 + bz0);
            float n = tanh_(x0 * wxn0 + x1 * wxn1 + bnx0 + r * (sN + bnh0));
            float h = n + z * (hprev0[i] - n);
            hprev0[i] = h;
            hp0n[kpj * 32 + (blf0 + i) * 2 + ej] = h;
        }
        GRPBAR(bar_id);   // h0(t) visible within group (only bar this step)

        // ==== G1: layer-1 GEMM. ks0: input side (w1 kp 0..31) over hp0[nxt];
        //          ks1: recurrent (w1 kp 32..63) over hp1[cur]. 32 kp each. ====
        u64 cR[8], cZ[8], cN[8];
        #pragma unroll
        for (int b = 0; b < 8; ++b) { cR[b] = 0; cZ[b] = 0; cN[b] = 0; }
        gemm_rzn<32>(w1rz, w1n, (ks ? hp1c : hp0n) + bgf, cR, cZ, cN);

        // ======== E1: exchange + gates; write h1(t) -> hp1[nxt] ========
        #pragma unroll
        for (int i = 0; i < 4; ++i) {
            u64 keepR = ks ? cR[4+i] : cR[i], sndR = ks ? cR[i] : cR[4+i];
            u64 keepZ = ks ? cZ[4+i] : cZ[i], sndZ = ks ? cZ[i] : cZ[4+i];
            u64 keepN = ks ? cN[4+i] : cN[i], sndN = ks ? cN[i] : cN[4+i];
            fadd2(keepR, __shfl_xor_sync(0xffffffffu, sndR, 16));
            fadd2(keepZ, __shfl_xor_sync(0xffffffffu, sndZ, 16));
            u64 rcvN = __shfl_xor_sync(0xffffffffu, sndN, 16);
            float sR = fold(keepR), sZ = fold(keepZ);
            float fm = fold(keepN), fr = fold(rcvN);
            float nx = ks ? fr : fm;      // input-side partial came from ks0
            float nh = ks ? fm : fr;      // recurrent partial came from ks1
            float r = sigm(sR + br1);
            float z = sigm(sZ + bz1);
            float n = tanh_(nx + bnx1 + r * (nh + bnh1));
            float h = n + z * (hprev1[i] - n);
            hprev1[i] = h;
            hp1n[kpj * 32 + (blf0 + i) * 2 + ej] = h;
        }
        // no second barrier: next step's bar (after E0) orders E1 stores
        // before G1(t+1) reads; G0(t+1) touches only hp0.
    }

    // ---- projection: out[b] = sum_j Wp[j]*h0f[j] + Wp[64+j]*h1f[j] + bp ----
    GRPBAR(bar_id);   // everyone in group done with h buffers
    {
        float* scr = hp0;   // reuse group h area: [16 b][stride 68]
        const float wp0 = Wp[j], wp1 = Wp[64 + j];
        #pragma unroll
        for (int i = 0; i < 4; ++i)
            scr[(blf0 + i) * 68 + j] = wp0 * hprev0[i] + wp1 * hprev1[i];
        GRPBAR(bar_id);
        if (gtid < 16) {
            float s = bp[0];
            #pragma unroll 8
            for (int jj = 0; jj < 64; ++jj) s += scr[gtid * 68 + jj];
            out[blockIdx.x * 32 + g * 16 + gtid] = s;
        }
    }
}

extern "C" void kernel_launch(void* const* d_in, const int* in_sizes, int n_in,
                              void* d_out, int out_size)
{
    (void)in_sizes; (void)n_in; (void)out_size;
    const float* x    = (const float*)d_in[0];
    const float* Wih0 = (const float*)d_in[1];
    const float* Whh0 = (const float*)d_in[2];
    const float* bih0 = (const float*)d_in[3];
    const float* bhh0 = (const float*)d_in[4];
    const float* Wih1 = (const float*)d_in[5];
    const float* Whh1 = (const float*)d_in[6];
    const float* bih1 = (const float*)d_in[7];
    const float* bhh1 = (const float*)d_in[8];
    const float* Wp   = (const float*)d_in[9];
    const float* bp   = (const float*)d_in[10];
    float* out = (float*)d_out;

    cudaFuncSetAttribute(gru2_kernel, cudaFuncAttributeMaxDynamicSharedMemorySize, SMEM_BYTES);
    gru2_kernel<<<NBLK, NTHR, SMEM_BYTES>>>(x, Wih0, Whh0, bih0, bhh0,
                                            Wih1, Whh1, bih1, bhh1, Wp, bp, out);
}